// round 17
// baseline (speedup 1.0000x reference)
#include <cuda_runtime.h>
#include <cstddef>

#define B_    256
#define T_    500
#define NIN_  128
#define NH_   512
#define NO_   64

// rec kernel smem: hs [512][20] + part [8*32][20]  (stride 20 -> float4-aligned)
#define HSTR2     20
#define HS_FL2    (NH_ * HSTR2)              // 10240 floats = 40960 B
#define PART_FL2  (8 * 32 * HSTR2)           // 5120 floats  = 20480 B
#define REC_SMEM2 ((HS_FL2 + PART_FL2) * 4)  // 61440 B -> 2 CTAs/SM

// ---------------------------------------------------------------------------
// Device scratch (no runtime allocation allowed)
// ---------------------------------------------------------------------------
__device__ __align__(16) float g_h[2 * NH_ * B_];   // ping-pong hidden, k-major [k][b]
__device__ __align__(16) float g_bias[NH_];         // b_ih + b_hh
__device__ unsigned g_flag[16 * 16 * 8];            // [gb][slice] monotonic, x8 pad

// ---------------------------------------------------------------------------
// f32x2 packed FMA helpers
// ---------------------------------------------------------------------------
__device__ __forceinline__ unsigned long long pack2(float lo, float hi) {
    unsigned long long r;
    asm("mov.b64 %0, {%1, %2};" : "=l"(r) : "f"(lo), "f"(hi));
    return r;
}
__device__ __forceinline__ void fma2(unsigned long long& d,
                                     unsigned long long a, unsigned long long b) {
    asm("fma.rn.f32x2 %0, %1, %2, %0;" : "+l"(d) : "l"(a), "l"(b));
}
__device__ __forceinline__ float2 unpack2(unsigned long long v) {
    float2 f;
    asm("mov.b64 {%0, %1}, %2;" : "=f"(f.x), "=f"(f.y) : "l"(v));
    return f;
}

union U4 { float4 v; unsigned long long p[2]; };

// ---------------------------------------------------------------------------
// Init: transpose h0 into g_h slot 0 (k-major), fold biases, reset flags.
// <<<NH_, B_>>>
// ---------------------------------------------------------------------------
__global__ void init_kernel(const float* __restrict__ h0,
                            const float* __restrict__ b_ih,
                            const float* __restrict__ b_hh) {
    int k = blockIdx.x;
    int b = threadIdx.x;
    g_h[(size_t)k * B_ + b] = h0[(size_t)b * NH_ + k];
    if (b == 0) g_bias[k] = b_ih[k] + b_hh[k];
    if (k == 0) g_flag[b * 8] = 0u;      // 256 flags
}

__global__ void nop_kernel() {}

// ---------------------------------------------------------------------------
// C[m][c] = sum_k A[m][k]*Bm[c][k] + bias[c]
// 128x64 tile, K-chunks of 32, 8x4 micro-tile per thread, f32x2 FMAs.
// ---------------------------------------------------------------------------
__global__ __launch_bounds__(256)
void gemm_bias_kernel(const float* __restrict__ A, const float* __restrict__ Bm,
                      const float* __restrict__ bias, float* __restrict__ C,
                      int K, int Ntot, int bias_mode) {
    __shared__ float xs[32][128];
    __shared__ float ws[32][64];

    const int tid = threadIdx.x;
    const int m0  = blockIdx.x * 128;
    const int c0  = blockIdx.y * 64;
    const int tx  = tid & 15;
    const int ty  = tid >> 4;

    const int arow = tid & 127, akq = tid >> 7;
    const int bcol = tid & 63,  bkh = tid >> 6;

    unsigned long long acc[16];
#pragma unroll
    for (int i = 0; i < 16; i++) acc[i] = 0ull;

    for (int kc = 0; kc < K; kc += 32) {
#pragma unroll
        for (int i = 0; i < 4; i++) {
            int kk = akq * 16 + i * 4;
            float4 v = *(const float4*)(A + (size_t)(m0 + arow) * K + kc + kk);
            xs[kk + 0][arow] = v.x; xs[kk + 1][arow] = v.y;
            xs[kk + 2][arow] = v.z; xs[kk + 3][arow] = v.w;
        }
#pragma unroll
        for (int i = 0; i < 2; i++) {
            int kk = bkh * 8 + i * 4;
            float4 v = *(const float4*)(Bm + (size_t)(c0 + bcol) * K + kc + kk);
            ws[kk + 0][bcol] = v.x; ws[kk + 1][bcol] = v.y;
            ws[kk + 2][bcol] = v.z; ws[kk + 3][bcol] = v.w;
        }
        __syncthreads();

#pragma unroll
        for (int kk = 0; kk < 32; kk++) {
            U4 a0, a1, b4;
            a0.v = *(const float4*)(&xs[kk][8 * ty]);
            a1.v = *(const float4*)(&xs[kk][8 * ty + 4]);
            b4.v = *(const float4*)(&ws[kk][4 * tx]);
            unsigned long long s0 = pack2(b4.v.x, b4.v.x);
            unsigned long long s1 = pack2(b4.v.y, b4.v.y);
            unsigned long long s2 = pack2(b4.v.z, b4.v.z);
            unsigned long long s3 = pack2(b4.v.w, b4.v.w);
            fma2(acc[0],  a0.p[0], s0); fma2(acc[1],  a0.p[1], s0);
            fma2(acc[2],  a1.p[0], s0); fma2(acc[3],  a1.p[1], s0);
            fma2(acc[4],  a0.p[0], s1); fma2(acc[5],  a0.p[1], s1);
            fma2(acc[6],  a1.p[0], s1); fma2(acc[7],  a1.p[1], s1);
            fma2(acc[8],  a0.p[0], s2); fma2(acc[9],  a0.p[1], s2);
            fma2(acc[10], a1.p[0], s2); fma2(acc[11], a1.p[1], s2);
            fma2(acc[12], a0.p[0], s3); fma2(acc[13], a0.p[1], s3);
            fma2(acc[14], a1.p[0], s3); fma2(acc[15], a1.p[1], s3);
        }
        __syncthreads();
    }

    const float* bp = bias_mode ? g_bias : bias;
    float4 bv = *(const float4*)(bp + c0 + 4 * tx);

#pragma unroll
    for (int i = 0; i < 4; i++) {
        float2 p0 = unpack2(acc[0 * 4 + i]);
        float2 p1 = unpack2(acc[1 * 4 + i]);
        float2 p2 = unpack2(acc[2 * 4 + i]);
        float2 p3 = unpack2(acc[3 * 4 + i]);
        float4 lo = make_float4(p0.x + bv.x, p1.x + bv.y, p2.x + bv.z, p3.x + bv.w);
        float4 hi = make_float4(p0.y + bv.x, p1.y + bv.y, p2.y + bv.z, p3.y + bv.w);
        size_t r0 = (size_t)(m0 + 8 * ty + 2 * i) * Ntot + c0 + 4 * tx;
        *(float4*)(C + r0)        = lo;
        *(float4*)(C + r0 + Ntot) = hi;
    }
}

// ---------------------------------------------------------------------------
// Persistent recurrence. 256 CTAs x 256 threads, 2 CTAs/SM.
// CTA(gb,cg): 16 batch rows x 32 cols. Warp g owns k-slice 64*((g+cg)&7);
// per-producer flag gating; 2 syncs/step; single tid-0 release; carried-h.
// ---------------------------------------------------------------------------
__global__ __launch_bounds__(256, 2)
void rnn_rec_kernel(const float* __restrict__ W_hh, const float* __restrict__ alpha,
                    float* __restrict__ outH, float* __restrict__ outF) {
    extern __shared__ float sm[];
    float* hs   = sm;               // [512][20] k-major h tile (warp-private rows)
    float* part = sm + HS_FL2;      // [8 g][32 c][20]

    const int tid  = threadIdx.x;
    const int lane = tid & 31;
    const int gb   = blockIdx.x & 15;      // batch group (16 rows)
    const int cg   = blockIdx.x >> 4;      // col group   (32 cols)
    const int g    = tid >> 5;             // warp id

    // ---- compute role: c = col within CTA (lane), warp g -> k slice ----
    const int c = lane;
    const int j = (g + cg) & 7;
    const int k_base = 64 * j;
    float w[64];
    {
        const float* wr = W_hh + (size_t)(cg * 32 + c) * NH_ + k_base;
#pragma unroll
        for (int i = 0; i < 16; i++) {
            float4 v = *(const float4*)(wr + 4 * i);
            w[4 * i] = v.x; w[4 * i + 1] = v.y; w[4 * i + 2] = v.z; w[4 * i + 3] = v.w;
        }
    }

    // ---- loader role: 8 LDG.128 per lane (64 k x 16 b) ----
    const int lq = lane & 3, lk = lane >> 2;

    // ---- reduce role: rrow = batch row (16), rc = col pair (16) ----
    const int rrow = tid & 15, rc = tid >> 4;
    const int c0g = cg * 32 + 2 * rc;            // first of 2 owned cols
    const int brow = gb * 16 + rrow;
    float2 av = *(const float2*)(alpha + c0g);
    const float al0 = av.x, al1 = av.y;
    const float om0 = 1.f - av.x, om1 = 1.f - av.y;

    // carried h (own 2 cols, own row) from slot 0 (h0 transposed)
    float ch0 = g_h[(size_t)(c0g + 0) * B_ + brow];
    float ch1 = g_h[(size_t)(c0g + 1) * B_ + brow];

    unsigned* myflag0 = &g_flag[(gb * 16 + 2 * j) * 8];
    unsigned* myflag1 = &g_flag[(gb * 16 + 2 * j + 1) * 8];
    unsigned* relflag = &g_flag[(gb * 16 + cg) * 8];

    for (int t = 0; t < T_; t++) {
        const float* hsrc = g_h + (size_t)(t & 1) * NH_ * B_;
        float*       hdst = g_h + (size_t)((t + 1) & 1) * NH_ * B_;

        // 0) prefetch pre (own 2-col slice of outH)
        const size_t haddr = ((size_t)brow * T_ + t) * NH_ + c0g;
        float2 pre = __ldcg((const float2*)(outH + haddr));

        // 1) per-warp gate: wait this warp's 2 producer flags
        if (t > 0) {
            if (lane < 2) {
                unsigned* fp = (lane == 0) ? myflag0 : myflag1;
                unsigned v;
                do {
                    asm volatile("ld.global.acquire.gpu.u32 %0, [%1];"
                                 : "=r"(v) : "l"(fp));
                } while (v < (unsigned)t);
            }
            __syncwarp();
        }

        // 2) per-warp load of its slice (64 k x 16 b) into hs
#pragma unroll
        for (int ii = 0; ii < 8; ii++) {
            int k = k_base + lk + 8 * ii;
            float4 v = __ldcg((const float4*)(hsrc + (size_t)k * B_ +
                                              gb * 16 + 4 * lq));
            *(float4*)(hs + (size_t)k * HSTR2 + 4 * lq) = v;
        }
        __syncwarp();

        // 3) partial GEMM: 64 k, 1 col, 16 rows per thread (broadcast LDS)
        unsigned long long a[8];
#pragma unroll
        for (int i = 0; i < 8; i++) a[i] = 0ull;
        const float* hbase = hs + (size_t)k_base * HSTR2;
#pragma unroll
        for (int kk = 0; kk < 64; kk++) {
            unsigned long long wsp = pack2(w[kk], w[kk]);
            const float* row = hbase + (size_t)kk * HSTR2;
#pragma unroll
            for (int q = 0; q < 4; q++) {
                U4 hv;
                hv.v = *(const float4*)(row + 4 * q);   // broadcast LDS.128
                fma2(a[2 * q],     hv.p[0], wsp);
                fma2(a[2 * q + 1], hv.p[1], wsp);
            }
        }
        {
            float* pb = part + (size_t)(g * 32 + c) * HSTR2;
#pragma unroll
            for (int q = 0; q < 4; q++) {
                float2 lo = unpack2(a[2 * q]);
                float2 hi = unpack2(a[2 * q + 1]);
                *(float4*)(pb + 4 * q) = make_float4(lo.x, lo.y, hi.x, hi.y);
            }
        }
        __syncthreads();

        // 4) reduce 8 k-groups for 2 cols, add pre, relu, leaky update
        float s0 = 0.f, s1 = 0.f;
        {
            const float* pb = part + (size_t)(2 * rc) * HSTR2 + rrow;
#pragma unroll
            for (int gg = 0; gg < 8; gg++) {
                const float* p = pb + (size_t)gg * (32 * HSTR2);
                s0 += p[0];
                s1 += p[HSTR2];
            }
        }
        float cc0 = fmaxf(s0 + pre.x, 0.f);
        float cc1 = fmaxf(s1 + pre.y, 0.f);
        ch0 = om0 * ch0 + al0 * cc0;
        ch1 = om1 * ch1 + al1 * cc1;

        // 5) publish h for next step, sync, release, then DRAM writes
        if (t < T_ - 1) {
            __stcg(hdst + (size_t)(c0g + 0) * B_ + brow, ch0);
            __stcg(hdst + (size_t)(c0g + 1) * B_ + brow, ch1);
        }
        __syncthreads();             // h stores + part reads complete CTA-wide
        if (t < T_ - 1 && tid == 0) {
            asm volatile("red.release.gpu.global.add.u32 [%0], %1;"
                         :: "l"(relflag), "r"(1u) : "memory");
        }
        float2 hn = make_float2(ch0, ch1);
        *(float2*)(outH + haddr) = hn;               // hidden_list (off path)
        if (t == T_ - 1)
            *(float2*)(outF + (size_t)brow * NH_ + c0g) = hn;
    }
}

// ---------------------------------------------------------------------------
extern "C" void kernel_launch(void* const* d_in, const int* in_sizes, int n_in,
                              void* d_out, int out_size) {
    const float* x     = (const float*)d_in[0];   // [B,T,128]
    const float* h0    = (const float*)d_in[1];   // [B,512]
    const float* Wih   = (const float*)d_in[2];   // [512,128]
    const float* Whh   = (const float*)d_in[3];   // [512,512]
    const float* bih   = (const float*)d_in[4];   // [512]
    const float* bhh   = (const float*)d_in[5];   // [512]
    const float* Wout  = (const float*)d_in[6];   // [64,512]
    const float* bout  = (const float*)d_in[7];   // [64]
    const float* alpha = (const float*)d_in[8];   // [512]

    float* out  = (float*)d_out;
    float* outH = out;                                   // hidden_list [B,T,512]
    float* outO = out + (size_t)B_ * T_ * NH_;           // output_list [B,T,64]
    float* outF = outO + (size_t)B_ * T_ * NO_;          // h_final     [B,512]

    cudaFuncSetAttribute(rnn_rec_kernel,
                         cudaFuncAttributeMaxDynamicSharedMemorySize, REC_SMEM2);

    // 1) init hidden transpose + bias fold + flag reset
    init_kernel<<<NH_, B_>>>(h0, bih, bhh);

    // 2) pre = x @ W_ih^T + (b_ih + b_hh), into hidden_list region (in-place)
    gemm_bias_kernel<<<dim3((B_ * T_) / 128, NH_ / 64), 256>>>(
        x, Wih, nullptr, outH, NIN_, NH_, 1);

    // 3) one nop so ncu (-s 5 -c 1) lands on the recurrence kernel
    nop_kernel<<<1, 1>>>();

    // 4) 500-step recurrence, 256 CTAs, 2 CTAs/SM
    rnn_rec_kernel<<<256, 256, REC_SMEM2>>>(Whh, alpha, outH, outF);

    // 5) output_list = hidden_list @ W_out^T + b_out
    gemm_bias_kernel<<<dim3((B_ * T_) / 128, NO_ / 64), 256>>>(
        outH, Wout, bout, outO, NH_, NO_, 0);
}